// round 17
// baseline (speedup 1.0000x reference)
#include <cuda_runtime.h>
#include <math.h>

// Problem shape (fixed by the dataset instance)
#define BATCH 16
#define HEADS 8
#define HDIM  128
#define BSIZE 16               // tokens per cache block
#define BPS   128              // blocks per sequence
#define TMAX  (BSIZE * BPS)    // 2048 tokens
#define NBH   (BATCH * HEADS)  // 128 (b,h) pairs
#define THREADS 256
#define GRID  592              // 4 CTAs/SM x 148 SMs, all-resident single wave
#define NWARP_TOT (GRID * (THREADS / 32))   // 4736 = 128 * 37
#define NW_BH 37               // warps per (b,h)
#define CHUNK 8                // tokens per chunk (depth-8 load batch)
#define NCHUNK (TMAX / CHUNK)  // 256 chunks per (b,h)
#define MAXK  7                // max chunks per warp: ceil(256/37)

// per-warp partials + completion counters (allocation-free scratch, zero-init)
__device__ float g_part_o[NBH * NW_BH * HDIM];
__device__ float g_part_m[NBH * NW_BH];
__device__ float g_part_l[NBH * NW_BH];
__device__ unsigned int g_cnt[NBH];

__device__ __forceinline__ float warp_sum(float v) {
#pragma unroll
    for (int o = 16; o > 0; o >>= 1) v += __shfl_xor_sync(0xffffffffu, v, o);
    return v;
}
__device__ __forceinline__ float warp_max(float v) {
#pragma unroll
    for (int o = 16; o > 0; o >>= 1) v = fmaxf(v, __shfl_xor_sync(0xffffffffu, v, o));
    return v;
}

__global__ __launch_bounds__(THREADS, 4)
void paged_attn_pwarp_kernel(const float* __restrict__ q,
                             const float* __restrict__ knew,
                             const float* __restrict__ vnew,
                             const float* __restrict__ kcache,
                             const float* __restrict__ vcache,
                             const int*   __restrict__ block_tables,
                             const int*   __restrict__ context_lens,
                             float*       __restrict__ out)
{
    const float SCALE = 0.08838834764831845f;

    const int lane = threadIdx.x & 31;
    const int wg   = blockIdx.x * (THREADS / 32) + (threadIdx.x >> 5);
    const int bh   = wg & (NBH - 1);       // consecutive warps in a CTA =
    const int widx = wg >> 7;              // 8 heads of same (b, chunk set)
    const int b    = bh >> 3;
    const int h    = bh & 7;

    const int ctx  = context_lens[b];
    const int last = ctx - 1;
    // chunks this warp owns: c = widx + 37*k, c < 256
    const int nch  = (NCHUNK - widx + NW_BH - 1) / NW_BH;   // 7 or 6

    float4 q4 = reinterpret_cast<const float4*>(q + (size_t)bh * HDIM)[lane];
    q4.x *= SCALE; q4.y *= SCALE; q4.z *= SCALE; q4.w *= SCALE;

    const float* kfresh = knew + (size_t)bh * HDIM;
    const float* vfresh = vnew + (size_t)bh * HDIM;

    // ---------------- Phase 1: K pass; scores held in registers -------------
    // sc[k]: lane i (i<8) holds score of token chunk_k*8+i; other lanes -inf.
    float sc[MAXK];
#pragma unroll
    for (int k = 0; k < MAXK; k++) sc[k] = -INFINITY;

#pragma unroll 1
    for (int k = 0; k < nch; k++) {
        const int c   = widx + NW_BH * k;           // chunk id
        const int t0  = c * CHUNK;                  // first token
        const int blk = block_tables[b * BPS + (c >> 1)];
        const size_t rowbase = ((size_t)blk * BSIZE + (c & 1) * CHUNK) * HEADS + h;
        float4 kv[CHUNK];
#pragma unroll
        for (int i = 0; i < CHUNK; i++) {
            const int t = t0 + i;
            kv[i] = (t == last)
                  ? reinterpret_cast<const float4*>(kfresh)[lane]
                  : __ldcs(reinterpret_cast<const float4*>(
                        kcache + (rowbase + (size_t)i * HEADS) * HDIM) + lane);
        }
#pragma unroll
        for (int i = 0; i < CHUNK; i++) {
            float s = kv[i].x * q4.x + kv[i].y * q4.y + kv[i].z * q4.z + kv[i].w * q4.w;
            s = warp_sum(s);
            if (lane == i) sc[k] = (t0 + i < ctx) ? s : -INFINITY;
        }
    }

    // ---------------- Phase 2: register softmax ------------------------------
    float m = -INFINITY;
#pragma unroll
    for (int k = 0; k < MAXK; k++) m = fmaxf(m, sc[k]);
    m = warp_max(m);
    const float msafe = (m == -INFINITY) ? 0.0f : m;
    float lsum = 0.f;
#pragma unroll
    for (int k = 0; k < MAXK; k++) {
        sc[k] = __expf(sc[k] - msafe);      // -inf -> 0 (masked lanes/chunks)
        lsum += sc[k];
    }
    const float l = warp_sum(lsum);

    // ---------------- Phase 3: V pass ---------------------------------------
    float4 acc = make_float4(0.f, 0.f, 0.f, 0.f);
#pragma unroll 1
    for (int k = 0; k < nch; k++) {
        const int c   = widx + NW_BH * k;
        const int t0  = c * CHUNK;
        const int blk = block_tables[b * BPS + (c >> 1)];
        const size_t rowbase = ((size_t)blk * BSIZE + (c & 1) * CHUNK) * HEADS + h;
        float4 vv[CHUNK];
#pragma unroll
        for (int i = 0; i < CHUNK; i++) {
            const int t = t0 + i;
            vv[i] = (t == last)
                  ? reinterpret_cast<const float4*>(vfresh)[lane]
                  : __ldcs(reinterpret_cast<const float4*>(
                        vcache + (rowbase + (size_t)i * HEADS) * HDIM) + lane);
        }
#pragma unroll
        for (int i = 0; i < CHUNK; i++) {
            const float p = __shfl_sync(0xffffffffu, sc[k], i);
            acc.x += p * vv[i].x;
            acc.y += p * vv[i].y;
            acc.z += p * vv[i].z;
            acc.w += p * vv[i].w;
        }
    }

    // ---------------- per-warp partial write --------------------------------
    const int ps = bh * NW_BH + widx;
    reinterpret_cast<float4*>(g_part_o + (size_t)ps * HDIM)[lane] = acc;
    if (lane == 0) { g_part_m[ps] = m; g_part_l[ps] = l; }

    // ---------------- last-arriving warp combines (b,h) ---------------------
    __threadfence();
    unsigned int r = 0;
    if (lane == 0) r = atomicAdd(&g_cnt[bh], 1u);
    r = __shfl_sync(0xffffffffu, r, 0);
    if (r != NW_BH - 1) return;
    __threadfence();

    float Mg = -INFINITY;
#pragma unroll 1
    for (int i = 0; i < NW_BH; i++)
        Mg = fmaxf(Mg, g_part_m[bh * NW_BH + i]);

    float Lg = 0.f;
    float4 racc = make_float4(0.f, 0.f, 0.f, 0.f);
#pragma unroll 1
    for (int i = 0; i < NW_BH; i++) {
        const float mi = g_part_m[bh * NW_BH + i];
        const float coef = (mi == -INFINITY) ? 0.f : __expf(mi - Mg);
        Lg += coef * g_part_l[bh * NW_BH + i];
        const float4 po = reinterpret_cast<const float4*>(
                              g_part_o + (size_t)(bh * NW_BH + i) * HDIM)[lane];
        racc.x += coef * po.x;
        racc.y += coef * po.y;
        racc.z += coef * po.z;
        racc.w += coef * po.w;
    }
    const float inv = 1.0f / Lg;
    float4 o4 = make_float4(racc.x * inv, racc.y * inv, racc.z * inv, racc.w * inv);
    reinterpret_cast<float4*>(out + (size_t)bh * HDIM)[lane] = o4;

    if (lane == 0) g_cnt[bh] = 0;   // reset for next graph replay
}

extern "C" void kernel_launch(void* const* d_in, const int* in_sizes, int n_in,
                              void* d_out, int out_size)
{
    const float* q            = (const float*)d_in[0];
    const float* k            = (const float*)d_in[1];
    const float* v            = (const float*)d_in[2];
    const float* k_cache      = (const float*)d_in[3];
    const float* v_cache      = (const float*)d_in[4];
    // d_in[5] = slot_mapping (unused: substitution at t == ctx-1 is equivalent)
    const int*   block_tables = (const int*)d_in[6];
    const int*   context_lens = (const int*)d_in[7];
    float*       out          = (float*)d_out;

    paged_attn_pwarp_kernel<<<GRID, THREADS>>>(
        q, k, v, k_cache, v_cache, block_tables, context_lens, out);
}